// round 1
// baseline (speedup 1.0000x reference)
#include <cuda_runtime.h>
#include <cstdint>
#include <cmath>

#define GH 512
#define GK 50
#define KPAD 52
#define GT 1024
#define GB 128
#define GM (GB * GT)
#define BPP 52

// Scratch for projected features [B*T, K]
__device__ float g_feats[(size_t)GM * GK];

// Packed fp32x2 FMA (sm_103a): acc = x * w + acc  (elementwise on 2 packed f32)
#define FFMA2(acc, x, w) \
    asm("fma.rn.f32x2 %0, %1, %2, %0;" : "+l"(acc) : "l"(x), "l"(w))

// ---------------------------------------------------------------------------
// Kernel 1: feats[m][k] = sum_h hidden[m][h] * W[k][h] + b[k]
// 256 CTAs x 256 threads, each thread computes 2 rows x 50 outputs.
// W transposed into smem as Wt[h][k] (row pad 52 -> 16B-aligned rows),
// loads are warp-broadcast LDS.128 (all lanes same address, conflict-free).
// ---------------------------------------------------------------------------
__global__ __launch_bounds__(256, 1) void gemm_kernel(
    const float* __restrict__ hidden, const float* __restrict__ W,
    const float* __restrict__ bias) {
    extern __shared__ float Wt[];  // [GH][KPAD]
    const int tid = threadIdx.x;

    // Load + transpose W: W[k*GH + h] -> Wt[h*KPAD + k] (coalesced gmem reads)
    for (int idx = tid; idx < GK * GH; idx += 256) {
        int k = idx / GH;
        int h = idx - k * GH;
        Wt[h * KPAD + k] = W[idx];
    }
    __syncthreads();

    const size_t base = (size_t)blockIdx.x * 512;
    const float4* r0 = reinterpret_cast<const float4*>(hidden + (base + tid) * GH);
    const float4* r1 = reinterpret_cast<const float4*>(hidden + (base + tid + 256) * GH);

    unsigned long long acc0[25], acc1[25];
#pragma unroll
    for (int q = 0; q < 25; q++) { acc0[q] = 0ull; acc1[q] = 0ull; }

    // Software-pipelined row loads: 8 h per chunk = 2 adjacent float4 per row
    // (adjacent 16B pairs fill full 32B sectors despite the 2KB lane stride).
    float4 a0 = r0[0], a1 = r0[1];
    float4 b0 = r1[0], b1 = r1[1];

    for (int hc = 0; hc < 64; hc++) {
        float xs0[8] = {a0.x, a0.y, a0.z, a0.w, a1.x, a1.y, a1.z, a1.w};
        float xs1[8] = {b0.x, b0.y, b0.z, b0.w, b1.x, b1.y, b1.z, b1.w};
        if (hc < 63) {
            a0 = r0[2 * hc + 2]; a1 = r0[2 * hc + 3];
            b0 = r1[2 * hc + 2]; b1 = r1[2 * hc + 3];
        }
#pragma unroll
        for (int u = 0; u < 8; u++) {
            const int h = hc * 8 + u;
            unsigned long long X0, X1;
            asm("mov.b64 %0, {%1, %1};" : "=l"(X0) : "r"(__float_as_uint(xs0[u])));
            asm("mov.b64 %0, {%1, %1};" : "=l"(X1) : "r"(__float_as_uint(xs1[u])));
            const float* wr = Wt + h * KPAD;
#pragma unroll
            for (int q = 0; q < 12; q++) {
                ulonglong2 w = *reinterpret_cast<const ulonglong2*>(wr + q * 4);
                FFMA2(acc0[2 * q],     X0, w.x);
                FFMA2(acc0[2 * q + 1], X0, w.y);
                FFMA2(acc1[2 * q],     X1, w.x);
                FFMA2(acc1[2 * q + 1], X1, w.y);
            }
            unsigned long long wl = *reinterpret_cast<const unsigned long long*>(wr + 48);
            FFMA2(acc0[24], X0, wl);
            FFMA2(acc1[24], X1, wl);
        }
    }

    // Epilogue: add bias, write feats rows (float2 stores, 8B aligned: 50 even)
    float2* o0 = reinterpret_cast<float2*>(g_feats + (base + tid) * GK);
    float2* o1 = reinterpret_cast<float2*>(g_feats + (base + tid + 256) * GK);
    const float2* bb = reinterpret_cast<const float2*>(bias);
#pragma unroll
    for (int q = 0; q < 25; q++) {
        float2 bv = bb[q];
        float2 v0 = *reinterpret_cast<float2*>(&acc0[q]);
        float2 v1 = *reinterpret_cast<float2*>(&acc1[q]);
        v0.x += bv.x; v0.y += bv.y;
        v1.x += bv.x; v1.y += bv.y;
        o0[q] = v0;
        o1[q] = v1;
    }
}

// ---------------------------------------------------------------------------
// Kernel 2: fused Viterbi forward + backtrace. One CTA per batch element.
// Thread (j, r): j = tid>>2 (output state), r = tid&3 (i-range split 4-way).
// Backpointers kept entirely in smem (1023 x 52 bytes) so the backtrace is
// a 29-cycle LDS pointer chase instead of an L2/DRAM chase.
// Tie-breaking matches jnp.argmax (first max): strict > over ascending i,
// merge prefers lower index on equal value.
// ---------------------------------------------------------------------------
__global__ __launch_bounds__(224, 1) void viterbi_kernel(
    const float* __restrict__ trans, const float* __restrict__ startt,
    const float* __restrict__ stopt, float* __restrict__ out) {
    extern __shared__ char sm[];
    unsigned char* bp = reinterpret_cast<unsigned char*>(sm);     // 1023*52
    float* vbuf = reinterpret_cast<float*>(sm + 53200);           // [2][64]
    float* red  = vbuf + 128;                                     // [64]

    const int b = blockIdx.x;
    const int tid = threadIdx.x;
    const int j = tid >> 2;
    const int r = tid & 3;
    const float* F = g_feats + (size_t)b * GT * GK;

    const int i0 = r * 13;
    const int cnt = (r == 3) ? 11 : 13;

    // Per-thread transition slice trans[i][j] for i in [i0, i0+cnt)
    float tr[13];
#pragma unroll
    for (int ii = 0; ii < 13; ii++)
        tr[ii] = (j < GK && ii < cnt) ? trans[(i0 + ii) * GK + j] : -INFINITY;

    // Pad unused state slots with -inf in both v buffers
    if (tid >= GK && tid < 64) { vbuf[tid] = -INFINITY; vbuf[64 + tid] = -INFINITY; }
    // v at t=0
    if (r == 0 && j < GK) vbuf[j] = F[j] + startt[j];

    // Feats prefetch ring, depth 4 (~600 cycles ahead ~ DRAM latency)
    float fr[4];
    if (r == 0 && j < GK) {
#pragma unroll
        for (int u = 0; u < 4; u++) fr[u] = F[(1 + u) * GK + j];
    }
    __syncthreads();

    for (int t = 1; t < GT; t += 4) {
#pragma unroll
        for (int u = 0; u < 4; u++) {
            const int tt = t + u;
            if (tt < GT) {  // uniform across block: barrier inside is legal
                const float* vr = vbuf + (((tt - 1) & 1) << 6);
                float best = -INFINITY;
                int bi = 0;
#pragma unroll
                for (int ii = 0; ii < 13; ii++) {
                    float s = vr[i0 + ii] + tr[ii];
                    if (s > best) { best = s; bi = i0 + ii; }
                }
                // Combine 4 partial (val, idx) across r via butterfly shuffles
                float ov = __shfl_xor_sync(0xffffffffu, best, 1);
                int   oi = __shfl_xor_sync(0xffffffffu, bi, 1);
                if (ov > best || (ov == best && oi < bi)) { best = ov; bi = oi; }
                ov = __shfl_xor_sync(0xffffffffu, best, 2);
                oi = __shfl_xor_sync(0xffffffffu, bi, 2);
                if (ov > best || (ov == best && oi < bi)) { best = ov; bi = oi; }

                if (r == 0 && j < GK) {
                    float* vw = vbuf + ((tt & 1) << 6);
                    vw[j] = fr[u] + best;
                    bp[(tt - 1) * BPP + j] = (unsigned char)bi;
                    int tn = tt + 4;
                    if (tn > GT - 1) tn = GT - 1;
                    fr[u] = F[tn * GK + j];
                }
                __syncthreads();
            }
        }
    }

    // Final state: v at t=1023 lives in buffer half 1 (1023 & 1)
    if (r == 0 && j < GK) red[j] = vbuf[64 + j] + stopt[j];
    __syncthreads();

    if (tid == 0) {
        float best = -INFINITY;
        int bj = 0;
        for (int k = 0; k < GK; k++) {
            float s = red[k];
            if (s > best) { best = s; bj = k; }
        }
        out[b] = best;
        float* tout = out + GB + (size_t)b * GT;
        int tag = bj;
        tout[GT - 1] = (float)tag;
        for (int k = GT - 2; k >= 0; k--) {
            tag = bp[k * BPP + tag];
            tout[k] = (float)tag;
        }
    }
}

extern "C" void kernel_launch(void* const* d_in, const int* in_sizes, int n_in,
                              void* d_out, int out_size) {
    const float* hidden = (const float*)d_in[0];
    const float* W      = (const float*)d_in[1];
    const float* bias   = (const float*)d_in[2];
    const float* trans  = (const float*)d_in[3];
    const float* startt = (const float*)d_in[4];
    const float* stopt  = (const float*)d_in[5];
    float* out = (float*)d_out;

    const size_t wsm = (size_t)GH * KPAD * sizeof(float);          // 106,496 B
    cudaFuncSetAttribute(gemm_kernel, cudaFuncAttributeMaxDynamicSharedMemorySize, (int)wsm);
    gemm_kernel<<<256, 256, wsm>>>(hidden, W, bias);

    const size_t vsm = 53200 + (128 + 64) * sizeof(float);         // 53,968 B
    cudaFuncSetAttribute(viterbi_kernel, cudaFuncAttributeMaxDynamicSharedMemorySize, (int)vsm);
    viterbi_kernel<<<GB, 224, vsm>>>(trans, startt, stopt, out);
}